// round 2
// baseline (speedup 1.0000x reference)
#include <cuda_runtime.h>
#include <cstdint>

using ull = unsigned long long;

#define D_IN           1024
#define BLOCK_THREADS  128
#define ROWS_PER_BLOCK 256
#define NBLOCKS        (65536 / ROWS_PER_BLOCK)   // 256

// ---------- packed f32x2 helpers ----------
__device__ __forceinline__ ull pack2(float v) {
    ull r;
    asm("mov.b64 %0, {%1, %1};" : "=l"(r) : "f"(v));
    return r;
}
__device__ __forceinline__ ull fma2(ull a, ull b, ull c) {
    ull d;
    asm("fma.rn.f32x2 %0, %1, %2, %3;" : "=l"(d) : "l"(a), "l"(b), "l"(c));
    return d;
}
__device__ __forceinline__ float2 unpack2(ull v) {
    float2 f;
    asm("mov.b64 {%0, %1}, %2;" : "=f"(f.x), "=f"(f.y) : "l"(v));
    return f;
}

// ---------- epilogue math ----------
__device__ __forceinline__ float softplus_f(float v) {
    // matches jax.nn.softplus: max(v,0) + log1p(exp(-|v|))
    return fmaxf(v, 0.0f) + log1pf(expf(-fabsf(v)));
}

__device__ __forceinline__ void rodrigues(float x, float y, float z, float* R) {
    float n2 = x * x + y * y + z * z;
    float th = sqrtf(n2);
    float inv = 1.0f / th;               // same singularity behavior as reference
    float ax = x * inv, ay = y * inv, az = z * inv;
    float st, ct;
    sincosf(th, &st, &ct);
    float oc = 1.0f - ct;
    R[0] = ct + oc * ax * ax; R[1] = oc * ax * ay - st * az; R[2] = oc * ax * az + st * ay;
    R[3] = oc * ax * ay + st * az; R[4] = ct + oc * ay * ay; R[5] = oc * ay * az - st * ax;
    R[6] = oc * ax * az - st * ay; R[7] = oc * ay * az + st * ax; R[8] = ct + oc * az * az;
}

__device__ __forceinline__ void finalize_row(
    int row,
    float s0, float s1, float s2, float s3, float s4,
    float s5, float s6, float s7, float s8,
    const float* __restrict__ eps,
    const float* __restrict__ bmu, const float* __restrict__ bd,
    const float* __restrict__ bl, float* __restrict__ out)
{
    float mu0 = s0 + bmu[0], mu1 = s1 + bmu[1], mu2 = s2 + bmu[2];
    float d0 = softplus_f(s3 + bd[0]);
    float d1 = softplus_f(s4 + bd[1]);
    float d2 = softplus_f(s5 + bd[2]);
    float l0 = s6 + bl[0], l1 = s7 + bl[1], l2 = s8 + bl[2];

    const float* e = eps + (size_t)row * 3;
    float t0 = sqrtf(d0) * e[0];
    float t1 = sqrtf(d1) * e[1];
    float t2 = sqrtf(d2) * e[2];

    float v0 = t0;
    float v1 = l0 * t0 + t1;
    float v2 = l1 * t0 + l2 * t1 + t2;

    float Rm[9], Rv[9];
    rodrigues(mu0, mu1, mu2, Rm);
    rodrigues(v0, v1, v2, Rv);

    float* o = out + (size_t)row * 9;
#pragma unroll
    for (int i = 0; i < 3; ++i) {
#pragma unroll
        for (int j = 0; j < 3; ++j) {
            o[i * 3 + j] = Rm[i * 3 + 0] * Rv[0 + j]
                         + Rm[i * 3 + 1] * Rv[3 + j]
                         + Rm[i * 3 + 2] * Rv[6 + j];
        }
    }
}

union F4U { float4 v; float f[4]; };

// One 16-k step: 16 k-values, 2 rows, accumulating into A[5]/B[5] packed pairs.
__device__ __forceinline__ void step16(const F4U* ca, const F4U* cb,
                                       const float* __restrict__ wf,
                                       ull* A, ull* B)
{
#pragma unroll
    for (int j = 0; j < 4; ++j) {
#pragma unroll
        for (int kk = 0; kk < 4; ++kk) {
            const float* w = wf + (j * 4 + kk) * 12;
            ulonglong2 wA = *(const ulonglong2*)w;        // (w0,w1),(w2,w3)
            ulonglong2 wB = *(const ulonglong2*)(w + 4);  // (w4,w5),(w6,w7)
            ull w8v = *(const ull*)(w + 8);               // (w8, 0)
            ull xad = pack2(ca[j].f[kk]);
            ull xbd = pack2(cb[j].f[kk]);
            A[0] = fma2(xad, wA.x, A[0]);
            A[1] = fma2(xad, wA.y, A[1]);
            A[2] = fma2(xad, wB.x, A[2]);
            A[3] = fma2(xad, wB.y, A[3]);
            A[4] = fma2(xad, w8v,  A[4]);
            B[0] = fma2(xbd, wA.x, B[0]);
            B[1] = fma2(xbd, wA.y, B[1]);
            B[2] = fma2(xbd, wB.x, B[2]);
            B[3] = fma2(xbd, wB.y, B[3]);
            B[4] = fma2(xbd, w8v,  B[4]);
        }
    }
}

__global__ __launch_bounds__(BLOCK_THREADS, 4)
void so3_stream_kernel(const float* __restrict__ x,
                       const float* __restrict__ eps,
                       const float* __restrict__ Wmu, const float* __restrict__ bmu,
                       const float* __restrict__ Wd,  const float* __restrict__ bd,
                       const float* __restrict__ Wl,  const float* __restrict__ bl,
                       float* __restrict__ out)
{
    __shared__ float wsm[D_IN * 12];     // 48 KB, exactly the static limit

    const int tid = threadIdx.x;
    const int rA  = blockIdx.x * ROWS_PER_BLOCK + tid;
    const int rB  = rA + BLOCK_THREADS;

    const float4* xa4 = (const float4*)(x + (size_t)rA * D_IN);
    const float4* xb4 = (const float4*)(x + (size_t)rB * D_IN);

    // Kick off the first x prefetch before weight staging so the DRAM pipe
    // is busy during the (one-time) staging + barrier.
    F4U ca[4], cb[4], na[4], nb[4];
#pragma unroll
    for (int j = 0; j < 4; ++j) { ca[j].v = xa4[j]; cb[j].v = xb4[j]; }

    // Stage packed weights: 12 floats per k -> pairs (w0,w1)(w2,w3)(w4,w5)(w6,w7)(w8,0)
    for (int k = tid; k < D_IN; k += BLOCK_THREADS) {
        float* o = wsm + k * 12;
        o[0] = Wmu[3 * k + 0]; o[1] = Wmu[3 * k + 1]; o[2] = Wmu[3 * k + 2];
        o[3] = Wd [3 * k + 0]; o[4] = Wd [3 * k + 1]; o[5] = Wd [3 * k + 2];
        o[6] = Wl [3 * k + 0]; o[7] = Wl [3 * k + 1]; o[8] = Wl [3 * k + 2];
        o[9] = 0.0f; o[10] = 0.0f; o[11] = 0.0f;
    }
    __syncthreads();   // the ONLY barrier in the kernel

    ull A[5] = {0, 0, 0, 0, 0};
    ull B[5] = {0, 0, 0, 0, 0};

    // 64 steps of 16 k each, register double-buffered, no barriers.
#pragma unroll 1
    for (int s = 0; s < 64; s += 2) {
#pragma unroll
        for (int j = 0; j < 4; ++j) {
            na[j].v = xa4[(s + 1) * 4 + j];
            nb[j].v = xb4[(s + 1) * 4 + j];
        }
        step16(ca, cb, wsm + s * 192, A, B);

        if (s + 2 < 64) {
#pragma unroll
            for (int j = 0; j < 4; ++j) {
                ca[j].v = xa4[(s + 2) * 4 + j];
                cb[j].v = xb4[(s + 2) * 4 + j];
            }
        }
        step16(na, nb, wsm + (s + 1) * 192, A, B);
    }

    // ---- epilogue: two rows per thread ----
    {
        float2 p0 = unpack2(A[0]), p1 = unpack2(A[1]), p2 = unpack2(A[2]),
               p3 = unpack2(A[3]), p4 = unpack2(A[4]);
        finalize_row(rA,
                     p0.x, p0.y, p1.x,   // mu raw
                     p1.y, p2.x, p2.y,   // d raw
                     p3.x, p3.y, p4.x,   // l raw
                     eps, bmu, bd, bl, out);
    }
    {
        float2 p0 = unpack2(B[0]), p1 = unpack2(B[1]), p2 = unpack2(B[2]),
               p3 = unpack2(B[3]), p4 = unpack2(B[4]);
        finalize_row(rB,
                     p0.x, p0.y, p1.x,
                     p1.y, p2.x, p2.y,
                     p3.x, p3.y, p4.x,
                     eps, bmu, bd, bl, out);
    }
}

extern "C" void kernel_launch(void* const* d_in, const int* in_sizes, int n_in,
                              void* d_out, int out_size)
{
    const float* x   = (const float*)d_in[0];
    const float* eps = (const float*)d_in[1];
    const float* Wmu = (const float*)d_in[2];
    const float* bmu = (const float*)d_in[3];
    const float* Wd  = (const float*)d_in[4];
    const float* bd  = (const float*)d_in[5];
    const float* Wl  = (const float*)d_in[6];
    const float* bl  = (const float*)d_in[7];
    float* out = (float*)d_out;

    so3_stream_kernel<<<NBLOCKS, BLOCK_THREADS>>>(
        x, eps, Wmu, bmu, Wd, bd, Wl, bl, out);
}

// round 4
// speedup vs baseline: 1.3973x; 1.3973x over previous
#include <cuda_runtime.h>
#include <cstdint>

using ull = unsigned long long;

#define D_IN           1024
#define BLOCK_THREADS  128
#define ROWS_PER_BLOCK 128
#define CHUNK_K        32
#define NCHUNK         (D_IN / CHUNK_K)        // 32
#define NSTAGES        4
#define NBLOCKS        (65536 / ROWS_PER_BLOCK) // 512

#define WSM_FLOATS     (D_IN * 10)                       // 40 KB
#define STAGE_FLOATS   (ROWS_PER_BLOCK * CHUNK_K)        // 4096 (16 KB)
#define SMEM_FLOATS    (WSM_FLOATS + NSTAGES * STAGE_FLOATS)
#define SMEM_BYTES     (SMEM_FLOATS * 4)                 // 104 KB

// ---------- packed f32x2 helpers ----------
__device__ __forceinline__ ull pack2(float v) {
    ull r;
    asm("mov.b64 %0, {%1, %1};" : "=l"(r) : "f"(v));
    return r;
}
__device__ __forceinline__ ull fma2(ull a, ull b, ull c) {
    ull d;
    asm("fma.rn.f32x2 %0, %1, %2, %3;" : "=l"(d) : "l"(a), "l"(b), "l"(c));
    return d;
}
__device__ __forceinline__ float2 unpack2(ull v) {
    float2 f;
    asm("mov.b64 {%0, %1}, %2;" : "=f"(f.x), "=f"(f.y) : "l"(v));
    return f;
}

// ---------- cp.async ----------
__device__ __forceinline__ void cp16(uint32_t smem_dst, const void* gsrc) {
    asm volatile("cp.async.cg.shared.global [%0], [%1], 16;\n"
                 :: "r"(smem_dst), "l"(gsrc));
}
__device__ __forceinline__ void cp_commit() {
    asm volatile("cp.async.commit_group;\n");
}

// ---------- epilogue math ----------
__device__ __forceinline__ float softplus_f(float v) {
    return fmaxf(v, 0.0f) + log1pf(expf(-fabsf(v)));
}

__device__ __forceinline__ void rodrigues(float x, float y, float z, float* R) {
    float n2 = x * x + y * y + z * z;
    float th = sqrtf(n2);
    float inv = 1.0f / th;               // same singularity behavior as reference
    float ax = x * inv, ay = y * inv, az = z * inv;
    float st, ct;
    sincosf(th, &st, &ct);
    float oc = 1.0f - ct;
    R[0] = ct + oc * ax * ax; R[1] = oc * ax * ay - st * az; R[2] = oc * ax * az + st * ay;
    R[3] = oc * ax * ay + st * az; R[4] = ct + oc * ay * ay; R[5] = oc * ay * az - st * ax;
    R[6] = oc * ax * az - st * ay; R[7] = oc * ay * az + st * ax; R[8] = ct + oc * az * az;
}

__device__ __forceinline__ void finalize_row(
    int row,
    float s0, float s1, float s2, float s3, float s4,
    float s5, float s6, float s7, float s8,
    const float* __restrict__ eps,
    const float* __restrict__ bmu, const float* __restrict__ bd,
    const float* __restrict__ bl, float* __restrict__ out)
{
    float mu0 = s0 + bmu[0], mu1 = s1 + bmu[1], mu2 = s2 + bmu[2];
    float d0 = softplus_f(s3 + bd[0]);
    float d1 = softplus_f(s4 + bd[1]);
    float d2 = softplus_f(s5 + bd[2]);
    float l0 = s6 + bl[0], l1 = s7 + bl[1], l2 = s8 + bl[2];

    const float* e = eps + (size_t)row * 3;
    float t0 = sqrtf(d0) * e[0];
    float t1 = sqrtf(d1) * e[1];
    float t2 = sqrtf(d2) * e[2];

    float v0 = t0;
    float v1 = l0 * t0 + t1;
    float v2 = l1 * t0 + l2 * t1 + t2;

    float Rm[9], Rv[9];
    rodrigues(mu0, mu1, mu2, Rm);
    rodrigues(v0, v1, v2, Rv);

    float* o = out + (size_t)row * 9;
#pragma unroll
    for (int i = 0; i < 3; ++i) {
#pragma unroll
        for (int j = 0; j < 3; ++j) {
            o[i * 3 + j] = Rm[i * 3 + 0] * Rv[0 + j]
                         + Rm[i * 3 + 1] * Rv[3 + j]
                         + Rm[i * 3 + 2] * Rv[6 + j];
        }
    }
}

union F4U { float4 v; float f[4]; };

// coalesced x-chunk loader: 128 rows x 128B, 8 lanes per row,
// 16B-chunk XOR swizzle (c ^ (row&7)) for conflict-free compute reads
__device__ __forceinline__ void load_chunk(const float* __restrict__ x,
                                           int rowbase, uint32_t xts,
                                           int tid, int chunk, int stage)
{
    const float* gx = x + (size_t)rowbase * D_IN + (size_t)chunk * CHUNK_K;
    uint32_t dbase = xts + (uint32_t)stage * (STAGE_FLOATS * 4);
#pragma unroll
    for (int it = 0; it < 8; ++it) {
        int idx = tid + it * BLOCK_THREADS;   // 0..1023
        int row = idx >> 3;
        int c   = idx & 7;
        uint32_t d = dbase + (uint32_t)(row * 128 + ((c ^ (row & 7)) << 4));
        cp16(d, gx + (size_t)row * D_IN + c * 4);
    }
    cp_commit();
}

__global__ __launch_bounds__(BLOCK_THREADS, 2)
void so3_pipe_kernel(const float* __restrict__ x,
                     const float* __restrict__ eps,
                     const float* __restrict__ Wmu, const float* __restrict__ bmu,
                     const float* __restrict__ Wd,  const float* __restrict__ bd,
                     const float* __restrict__ Wl,  const float* __restrict__ bl,
                     float* __restrict__ out)
{
    extern __shared__ float smem[];
    float* wsm = smem;                  // 1024 x 10 packed weights
    float* xt  = smem + WSM_FLOATS;     // NSTAGES x (128 rows x 32 floats)

    const int tid = threadIdx.x;
    const int rowbase = blockIdx.x * ROWS_PER_BLOCK;
    const uint32_t xts = (uint32_t)__cvta_generic_to_shared(xt);

    // prologue: fill NSTAGES-1 stages before anything else (overlaps weight staging)
    load_chunk(x, rowbase, xts, tid, 0, 0);
    load_chunk(x, rowbase, xts, tid, 1, 1);
    load_chunk(x, rowbase, xts, tid, 2, 2);

    // stage packed weights: 10 floats per k: (w0,w1)(w2,w3)(w4,w5)(w6,w7)(w8,0)
    for (int k = tid; k < D_IN; k += BLOCK_THREADS) {
        float* o = wsm + k * 10;
        o[0] = Wmu[3 * k + 0]; o[1] = Wmu[3 * k + 1]; o[2] = Wmu[3 * k + 2];
        o[3] = Wd [3 * k + 0]; o[4] = Wd [3 * k + 1]; o[5] = Wd [3 * k + 2];
        o[6] = Wl [3 * k + 0]; o[7] = Wl [3 * k + 1]; o[8] = Wl [3 * k + 2];
        o[9] = 0.0f;
    }

    const int q = tid & 7;
    ull A0 = 0, A1 = 0, A2 = 0, A3 = 0, A4 = 0;

#pragma unroll 1
    for (int c = 0; c < NCHUNK; ++c) {
        asm volatile("cp.async.wait_group 2;\n");   // chunk c resident
        __syncthreads();                             // visible to all; prev compute done

        // refill the stage freed by chunk c-1 (empty commit keeps accounting exact)
        if (c + NSTAGES - 1 < NCHUNK) {
            load_chunk(x, rowbase, xts, tid, c + NSTAGES - 1,
                       (c + NSTAGES - 1) & (NSTAGES - 1));
        } else {
            cp_commit();
        }

        const float* xrow = xt + (size_t)(c & (NSTAGES - 1)) * STAGE_FLOATS
                               + (size_t)tid * CHUNK_K;
        const float* wp = wsm + c * (CHUNK_K * 10);

#pragma unroll
        for (int j = 0; j < 8; ++j) {
            F4U x4;
            x4.v = *(const float4*)(xrow + ((j ^ q) << 2));
#pragma unroll
            for (int kk = 0; kk < 4; ++kk) {
                const float* w = wp + (j * 4 + kk) * 10;
                ull w01 = *(const ull*)(w + 0);
                ull w23 = *(const ull*)(w + 2);
                ull w45 = *(const ull*)(w + 4);
                ull w67 = *(const ull*)(w + 6);
                ull w8v = *(const ull*)(w + 8);
                ull xd  = pack2(x4.f[kk]);
                A0 = fma2(xd, w01, A0);
                A1 = fma2(xd, w23, A1);
                A2 = fma2(xd, w45, A2);
                A3 = fma2(xd, w67, A3);
                A4 = fma2(xd, w8v, A4);
            }
        }
    }

    // ---- epilogue: one row per thread ----
    float2 p0 = unpack2(A0), p1 = unpack2(A1), p2 = unpack2(A2),
           p3 = unpack2(A3), p4 = unpack2(A4);
    finalize_row(rowbase + tid,
                 p0.x, p0.y, p1.x,   // mu raw
                 p1.y, p2.x, p2.y,   // d raw
                 p3.x, p3.y, p4.x,   // l raw
                 eps, bmu, bd, bl, out);
}

extern "C" void kernel_launch(void* const* d_in, const int* in_sizes, int n_in,
                              void* d_out, int out_size)
{
    const float* x   = (const float*)d_in[0];
    const float* eps = (const float*)d_in[1];
    const float* Wmu = (const float*)d_in[2];
    const float* bmu = (const float*)d_in[3];
    const float* Wd  = (const float*)d_in[4];
    const float* bd  = (const float*)d_in[5];
    const float* Wl  = (const float*)d_in[6];
    const float* bl  = (const float*)d_in[7];
    float* out = (float*)d_out;

    cudaFuncSetAttribute(so3_pipe_kernel,
                         cudaFuncAttributeMaxDynamicSharedMemorySize, SMEM_BYTES);

    so3_pipe_kernel<<<NBLOCKS, BLOCK_THREADS, SMEM_BYTES>>>(
        x, eps, Wmu, bmu, Wd, bd, Wl, bl, out);
}